// round 3
// baseline (speedup 1.0000x reference)
#include <cuda_runtime.h>
#include <cuda_bf16.h>
#include <cstdint>

// Problem constants (fixed by the reference setup_inputs)
#define NN 8192          // nodes
#define DD 128           // feature dim
#define MAXNB 512        // per-row neighbor capacity
#define NEG_SLOPE 0.2f

#define GEMM_BLOCKS 256          // 8192 / BM, BM = 32
#define BUILD_BLOCKS 1024        // 8192 warps / 8 warps-per-block

// ---------------- device scratch (no allocations allowed) ----------------
__device__ float g_h[(size_t)NN * DD];
__device__ float g_asrc[NN];
__device__ float g_adst[NN];
__device__ int   g_col[(size_t)NN * MAXNB];
__device__ int   g_cnt[NN];

// ---------------- adjacency scan body (device function) -------------------
__device__ __forceinline__ void build_row(const float* __restrict__ adj, int row_id, int lane) {
    const float4* row = reinterpret_cast<const float4*>(adj + (size_t)row_id * NN);
    int* col = g_col + (size_t)row_id * MAXNB;
    const unsigned ltmask = (1u << lane) - 1u;
    int cnt = 0;
    #pragma unroll 2
    for (int j0 = 0; j0 < NN; j0 += 128) {
        float4 v = row[(j0 >> 2) + lane];
        int base = j0 + lane * 4;
        unsigned m0 = __ballot_sync(0xffffffffu, v.x != 0.0f);
        unsigned m1 = __ballot_sync(0xffffffffu, v.y != 0.0f);
        unsigned m2 = __ballot_sync(0xffffffffu, v.z != 0.0f);
        unsigned m3 = __ballot_sync(0xffffffffu, v.w != 0.0f);
        if (v.x != 0.0f) { int p = cnt + __popc(m0 & ltmask); if (p < MAXNB) col[p] = base + 0; }
        cnt += __popc(m0);
        if (v.y != 0.0f) { int p = cnt + __popc(m1 & ltmask); if (p < MAXNB) col[p] = base + 1; }
        cnt += __popc(m1);
        if (v.z != 0.0f) { int p = cnt + __popc(m2 & ltmask); if (p < MAXNB) col[p] = base + 2; }
        cnt += __popc(m2);
        if (v.w != 0.0f) { int p = cnt + __popc(m3 & ltmask); if (p < MAXNB) col[p] = base + 3; }
        cnt += __popc(m3);
    }
    if (lane == 0) g_cnt[row_id] = cnt < MAXNB ? cnt : MAXNB;
}

// ---------------- GEMM body: H[rowBase:rowBase+32] = X @ W + attn epilogue -
// BM=32, BN=128, BK=16, 256 threads, 2x8 outputs/thread.
__device__ __forceinline__ void gemm_tile(const float* __restrict__ X,
                                          const float* __restrict__ W,
                                          const float* __restrict__ att_src,
                                          const float* __restrict__ att_dst,
                                          float* __restrict__ H,
                                          int rowBase) {
    __shared__ float As[16][32];
    __shared__ float Bs[16][128];
    const int tid = threadIdx.x;
    const int tx = tid & 15;        // col group (8 cols)
    const int ty = tid >> 4;        // row group (2 rows each)

    float acc[2][8];
    #pragma unroll
    for (int i = 0; i < 2; i++)
        #pragma unroll
        for (int j = 0; j < 8; j++) acc[i][j] = 0.0f;

    for (int k0 = 0; k0 < DD; k0 += 16) {
        {   // A tile: 32 rows x 16 k -> one float2 per thread
            int r  = tid >> 3;
            int kq = (tid & 7) * 2;
            float2 v = *reinterpret_cast<const float2*>(
                &X[(size_t)(rowBase + r) * DD + k0 + kq]);
            As[kq + 0][r] = v.x;
            As[kq + 1][r] = v.y;
        }
        {   // B tile: 16 k x 128 n -> two float4 per thread
            int kr = tid >> 4;
            int cq = (tid & 15) * 8;
            const float* src = &W[(size_t)(k0 + kr) * DD + cq];
            float4 v0 = *reinterpret_cast<const float4*>(src);
            float4 v1 = *reinterpret_cast<const float4*>(src + 4);
            *reinterpret_cast<float4*>(&Bs[kr][cq])     = v0;
            *reinterpret_cast<float4*>(&Bs[kr][cq + 4]) = v1;
        }
        __syncthreads();
        #pragma unroll
        for (int k = 0; k < 16; k++) {
            float a[2], b[8];
            a[0] = As[k][ty * 2 + 0];
            a[1] = As[k][ty * 2 + 1];
            #pragma unroll
            for (int j = 0; j < 8; j++) b[j] = Bs[k][tx * 8 + j];
            #pragma unroll
            for (int i = 0; i < 2; i++)
                #pragma unroll
                for (int j = 0; j < 8; j++) acc[i][j] = fmaf(a[i], b[j], acc[i][j]);
        }
        __syncthreads();
    }

    // store H tile
    #pragma unroll
    for (int i = 0; i < 2; i++) {
        float* dst = &H[(size_t)(rowBase + ty * 2 + i) * DD + tx * 8];
        *reinterpret_cast<float4*>(dst)     = make_float4(acc[i][0], acc[i][1], acc[i][2], acc[i][3]);
        *reinterpret_cast<float4*>(dst + 4) = make_float4(acc[i][4], acc[i][5], acc[i][6], acc[i][7]);
    }

    // fused attention coefficients (reduce over tx within 16-lane half-warps)
    float as[8], ad[8];
    {
        float4 s0 = *reinterpret_cast<const float4*>(&att_src[tx * 8]);
        float4 s1 = *reinterpret_cast<const float4*>(&att_src[tx * 8 + 4]);
        float4 d0 = *reinterpret_cast<const float4*>(&att_dst[tx * 8]);
        float4 d1 = *reinterpret_cast<const float4*>(&att_dst[tx * 8 + 4]);
        as[0]=s0.x; as[1]=s0.y; as[2]=s0.z; as[3]=s0.w;
        as[4]=s1.x; as[5]=s1.y; as[6]=s1.z; as[7]=s1.w;
        ad[0]=d0.x; ad[1]=d0.y; ad[2]=d0.z; ad[3]=d0.w;
        ad[4]=d1.x; ad[5]=d1.y; ad[6]=d1.z; ad[7]=d1.w;
    }
    #pragma unroll
    for (int i = 0; i < 2; i++) {
        float ps = 0.0f, pd = 0.0f;
        #pragma unroll
        for (int j = 0; j < 8; j++) {
            ps = fmaf(acc[i][j], as[j], ps);
            pd = fmaf(acc[i][j], ad[j], pd);
        }
        #pragma unroll
        for (int o = 8; o > 0; o >>= 1) {
            ps += __shfl_xor_sync(0xffffffffu, ps, o);
            pd += __shfl_xor_sync(0xffffffffu, pd, o);
        }
        if (tx == 0) {
            g_asrc[rowBase + ty * 2 + i] = ps;
            g_adst[rowBase + ty * 2 + i] = pd;
        }
    }
}

// ---------------- fused: layer-0 GEMM + adjacency scan (independent) ------
__global__ __launch_bounds__(256) void fused_gemm_build(const float* __restrict__ X,
                                                        const float* __restrict__ W,
                                                        const float* __restrict__ att_src,
                                                        const float* __restrict__ att_dst,
                                                        float* __restrict__ H,
                                                        const float* __restrict__ adj) {
    if (blockIdx.x < GEMM_BLOCKS) {
        gemm_tile(X, W, att_src, att_dst, H, blockIdx.x * 32);
    } else {
        int row_id = ((blockIdx.x - GEMM_BLOCKS) * 256 + threadIdx.x) >> 5;
        build_row(adj, row_id, threadIdx.x & 31);
    }
}

// ---------------- standalone GEMM (layer 1) --------------------------------
__global__ __launch_bounds__(256) void gemm_xw(const float* __restrict__ X,
                                               const float* __restrict__ W,
                                               const float* __restrict__ att_src,
                                               const float* __restrict__ att_dst,
                                               float* __restrict__ H) {
    gemm_tile(X, W, att_src, att_dst, H, blockIdx.x * 32);
}

// ---------------- masked softmax + sparse aggregation ----------------------
__global__ __launch_bounds__(128) void aggregate(const float* __restrict__ H,
                                                 const float* __restrict__ bias,
                                                 float* __restrict__ out,
                                                 int do_relu) {
    const int i    = blockIdx.x;
    const int tid  = threadIdx.x;
    const int lane = tid & 31;
    const int w    = tid >> 5;
    __shared__ float se[MAXNB];
    __shared__ int   sc[MAXNB];
    __shared__ float redm[4];
    __shared__ float reds[4];
    __shared__ float accs[4][DD];

    const int cnt = g_cnt[i];
    const float adst_i = g_adst[i];

    // phase A: gather neighbor logits, leaky relu, local max
    float lmax = -1e30f;
    for (int k = tid; k < cnt; k += 128) {
        int j = g_col[(size_t)i * MAXNB + k];
        sc[k] = j;
        float e = g_asrc[j] + adst_i;
        e = e >= 0.0f ? e : NEG_SLOPE * e;
        se[k] = e;
        lmax = fmaxf(lmax, e);
    }
    #pragma unroll
    for (int o = 16; o > 0; o >>= 1)
        lmax = fmaxf(lmax, __shfl_xor_sync(0xffffffffu, lmax, o));
    if (lane == 0) redm[w] = lmax;
    __syncthreads();
    const float m = fmaxf(fmaxf(redm[0], redm[1]), fmaxf(redm[2], redm[3]));

    // phase B: exp + sum
    float lsum = 0.0f;
    for (int k = tid; k < cnt; k += 128) {
        float wv = __expf(se[k] - m);
        se[k] = wv;
        lsum += wv;
    }
    #pragma unroll
    for (int o = 16; o > 0; o >>= 1)
        lsum += __shfl_xor_sync(0xffffffffu, lsum, o);
    if (lane == 0) reds[w] = lsum;
    __syncthreads();
    const float inv = 1.0f / (reds[0] + reds[1] + reds[2] + reds[3]);

    // phase C: weighted sum of neighbor feature rows, float4 per lane
    const float4* H4 = reinterpret_cast<const float4*>(H);
    float4 a = make_float4(0.0f, 0.0f, 0.0f, 0.0f);
    int k = w;
    for (; k + 8 <= cnt; k += 8) {
        float w0 = se[k],     w1 = se[k + 4];
        int   j0 = sc[k],     j1 = sc[k + 4];
        float4 v0 = H4[(size_t)j0 * 32 + lane];
        float4 v1 = H4[(size_t)j1 * 32 + lane];
        a.x = fmaf(w0, v0.x, a.x); a.y = fmaf(w0, v0.y, a.y);
        a.z = fmaf(w0, v0.z, a.z); a.w = fmaf(w0, v0.w, a.w);
        a.x = fmaf(w1, v1.x, a.x); a.y = fmaf(w1, v1.y, a.y);
        a.z = fmaf(w1, v1.z, a.z); a.w = fmaf(w1, v1.w, a.w);
    }
    for (; k < cnt; k += 4) {
        float w0 = se[k];
        float4 v0 = H4[(size_t)sc[k] * 32 + lane];
        a.x = fmaf(w0, v0.x, a.x); a.y = fmaf(w0, v0.y, a.y);
        a.z = fmaf(w0, v0.z, a.z); a.w = fmaf(w0, v0.w, a.w);
    }
    *reinterpret_cast<float4*>(&accs[w][lane * 4]) = a;
    __syncthreads();

    float s = accs[0][tid] + accs[1][tid] + accs[2][tid] + accs[3][tid];
    float o = s * inv + bias[tid];
    if (do_relu) o = fmaxf(o, 0.0f);
    out[(size_t)i * DD + tid] = o;
}

// ---------------- launch ---------------------------------------------------
extern "C" void kernel_launch(void* const* d_in, const int* in_sizes, int n_in,
                              void* d_out, int out_size) {
    const float* x        = (const float*)d_in[0];
    const float* adj      = (const float*)d_in[1];
    const float* W0       = (const float*)d_in[2];
    const float* att_src0 = (const float*)d_in[3];
    const float* att_dst0 = (const float*)d_in[4];
    const float* b0       = (const float*)d_in[5];
    const float* W1       = (const float*)d_in[6];
    const float* att_src1 = (const float*)d_in[7];
    const float* att_dst1 = (const float*)d_in[8];
    const float* b1       = (const float*)d_in[9];

    float* out0 = (float*)d_out;
    float* out1 = (float*)d_out + (size_t)NN * DD;

    float* h;
    cudaGetSymbolAddress((void**)&h, g_h);

    // layer-0 GEMM runs concurrently with the adjacency scan (independent)
    fused_gemm_build<<<GEMM_BLOCKS + BUILD_BLOCKS, 256>>>(x, W0, att_src0, att_dst0, h, adj);
    aggregate<<<NN, 128>>>(h, b0, out0, 1);

    gemm_xw<<<GEMM_BLOCKS, 256>>>(out0, W1, att_src1, att_dst1, h);
    aggregate<<<NN, 128>>>(h, b1, out1, 0);
}